// round 1
// baseline (speedup 1.0000x reference)
#include <cuda_runtime.h>
#include <math.h>

#define NN 20000
#define NE 320000
#define NEP 340000      // NE + NN self loops
#define NHEAD 4
#define NEG_SLOPE 0.2f

// ---------------- scratch (static device globals; no runtime alloc) ----------------
__device__ int   g_deg[NN];
__device__ int   g_rowptr[NN + 1];
__device__ int   g_wptr[NN];
__device__ float g_dis[NN];
__device__ int   g_src[NEP];
__device__ int   g_eid[NEP];
__device__ float g_xw[NN * 256];
__device__ float g_h0[NN * 64];
__device__ float g_h1[NN * 256];
__device__ float g_h2[NN * 64];
__device__ float g_als[NN * 4];
__device__ float g_ald[NN * 4];
__device__ float g_alpha[NEP * 4];

// ---------------- graph build ----------------
__global__ void k_zero_deg() {
    for (int i = blockIdx.x * blockDim.x + threadIdx.x; i < NN; i += gridDim.x * blockDim.x)
        g_deg[i] = 0;
}

__global__ void k_hist(const int* __restrict__ ei) {
    for (int e = blockIdx.x * blockDim.x + threadIdx.x; e < NEP; e += gridDim.x * blockDim.x) {
        int d = (e < NE) ? ei[NE + e] : (e - NE);
        atomicAdd(&g_deg[d], 1);
    }
}

// single block, 1024 threads: exclusive scan of degrees -> rowptr, wptr, dis
__global__ void k_scan() {
    __shared__ int tmp[1024];
    const int tid = threadIdx.x;
    const int CH = (NN + 1023) / 1024;   // 20
    const int base = tid * CH;
    int sum = 0;
    for (int i = 0; i < CH; i++) {
        int n = base + i;
        if (n < NN) sum += g_deg[n];
    }
    tmp[tid] = sum;
    __syncthreads();
    for (int off = 1; off < 1024; off <<= 1) {
        int v = (tid >= off) ? tmp[tid - off] : 0;
        __syncthreads();
        tmp[tid] += v;
        __syncthreads();
    }
    int run = tmp[tid] - sum;   // exclusive prefix
    for (int i = 0; i < CH; i++) {
        int n = base + i;
        if (n < NN) {
            int c = g_deg[n];
            g_rowptr[n] = run;
            g_wptr[n]   = run;
            g_dis[n]    = (c > 0) ? rsqrtf((float)c) : 0.0f;
            run += c;
        }
    }
    if (tid == 1023) g_rowptr[NN] = run;
}

__global__ void k_scatter(const int* __restrict__ ei) {
    for (int e = blockIdx.x * blockDim.x + threadIdx.x; e < NEP; e += gridDim.x * blockDim.x) {
        int s, d;
        if (e < NE) { s = ei[e]; d = ei[NE + e]; }
        else        { s = e - NE; d = e - NE; }
        int pos = atomicAdd(&g_wptr[d], 1);
        g_src[pos] = s;
        g_eid[pos] = e;
    }
}

// ---------------- GEMM: C[M,N] = A[M,K] @ W[K,N]  (row-major, K,N mult of 16/64) ----------------
__global__ void k_gemm(const float* __restrict__ A, const float* __restrict__ W,
                       float* __restrict__ C, int M, int K, int N) {
    __shared__ float As[16][64];
    __shared__ float Ws[16][64];
    const int tid = threadIdx.x;            // 256 threads
    const int tx = tid & 15, ty = tid >> 4; // 16x16
    const int row0 = blockIdx.x * 64;
    const int col0 = blockIdx.y * 64;
    float acc[4][4];
#pragma unroll
    for (int i = 0; i < 4; i++)
#pragma unroll
        for (int j = 0; j < 4; j++) acc[i][j] = 0.0f;

    for (int k0 = 0; k0 < K; k0 += 16) {
#pragma unroll
        for (int i = 0; i < 4; i++) {
            int e = tid + i * 256;
            int r = e >> 4, c = e & 15;
            int gr = row0 + r;
            As[c][r] = (gr < M) ? A[(long)gr * K + k0 + c] : 0.0f;
        }
#pragma unroll
        for (int i = 0; i < 4; i++) {
            int e = tid + i * 256;
            int r = e >> 6, c = e & 63;
            Ws[r][c] = W[(long)(k0 + r) * N + col0 + c];
        }
        __syncthreads();
#pragma unroll
        for (int k = 0; k < 16; k++) {
            float a[4], b[4];
#pragma unroll
            for (int i = 0; i < 4; i++) a[i] = As[k][ty * 4 + i];
#pragma unroll
            for (int j = 0; j < 4; j++) b[j] = Ws[k][tx * 4 + j];
#pragma unroll
            for (int i = 0; i < 4; i++)
#pragma unroll
                for (int j = 0; j < 4; j++) acc[i][j] = fmaf(a[i], b[j], acc[i][j]);
        }
        __syncthreads();
    }
#pragma unroll
    for (int i = 0; i < 4; i++) {
        int gr = row0 + ty * 4 + i;
        if (gr < M) {
#pragma unroll
            for (int j = 0; j < 4; j++)
                C[(long)gr * N + col0 + tx * 4 + j] = acc[i][j];
        }
    }
}

static inline void launch_gemm(const float* A, const float* W, float* C, int M, int K, int N) {
    dim3 grid((M + 63) / 64, N / 64);
    k_gemm<<<grid, 256>>>(A, W, C, M, K, N);
}

// ---------------- GCN aggregate: block(64) per node ----------------
__global__ void k_gcn_agg(const float* __restrict__ xw, const float* __restrict__ b,
                          float* __restrict__ out) {
    int n = blockIdx.x, t = threadIdx.x;
    int beg = g_rowptr[n], end = g_rowptr[n + 1];
    float dn = g_dis[n];
    float acc = 0.0f;
    for (int j = beg; j < end; j++) {
        int s = g_src[j];
        acc = fmaf(dn * g_dis[s], xw[s * 64 + t], acc);
    }
    out[n * 64 + t] = fmaxf(acc + b[t], 0.0f);
}

// ---------------- attention coefficients: block(64) per node ----------------
__global__ void k_coef(const float* __restrict__ xw, const float* __restrict__ asrc,
                       const float* __restrict__ adst) {
    int n = blockIdx.x, t = threadIdx.x;
    int h = t >> 4, q = t & 15;
    const float4 v  = *(const float4*)(xw + (long)n * 256 + h * 64 + q * 4);
    const float4 ws = *(const float4*)(asrc + h * 64 + q * 4);
    const float4 wd = *(const float4*)(adst + h * 64 + q * 4);
    float ps = v.x * ws.x + v.y * ws.y + v.z * ws.z + v.w * ws.w;
    float pd = v.x * wd.x + v.y * wd.y + v.z * wd.z + v.w * wd.w;
#pragma unroll
    for (int off = 8; off > 0; off >>= 1) {
        ps += __shfl_down_sync(0xffffffffu, ps, off, 16);
        pd += __shfl_down_sync(0xffffffffu, pd, off, 16);
    }
    if (q == 0) {
        g_als[n * 4 + h] = ps;
        g_ald[n * 4 + h] = pd;
    }
}

__device__ __forceinline__ float leaky(float x) { return x > 0.0f ? x : NEG_SLOPE * x; }

// ---------------- per-node segment softmax: 1 warp per node (4 warps/block) ----------------
__global__ void k_softmax(float* __restrict__ alpha_out) {
    int warp = threadIdx.x >> 5, lane = threadIdx.x & 31;
    int n = blockIdx.x * 4 + warp;
    if (n >= NN) return;
    int beg = g_rowptr[n], end = g_rowptr[n + 1];
    float4 ad = *(const float4*)(g_ald + n * 4);

    float m0 = -1e30f, m1 = -1e30f, m2 = -1e30f, m3 = -1e30f;
    for (int j = beg + lane; j < end; j += 32) {
        int s = g_src[j];
        float4 as4 = *(const float4*)(g_als + s * 4);
        m0 = fmaxf(m0, leaky(as4.x + ad.x));
        m1 = fmaxf(m1, leaky(as4.y + ad.y));
        m2 = fmaxf(m2, leaky(as4.z + ad.z));
        m3 = fmaxf(m3, leaky(as4.w + ad.w));
    }
#pragma unroll
    for (int off = 16; off > 0; off >>= 1) {
        m0 = fmaxf(m0, __shfl_xor_sync(0xffffffffu, m0, off));
        m1 = fmaxf(m1, __shfl_xor_sync(0xffffffffu, m1, off));
        m2 = fmaxf(m2, __shfl_xor_sync(0xffffffffu, m2, off));
        m3 = fmaxf(m3, __shfl_xor_sync(0xffffffffu, m3, off));
    }
    float s0 = 0, s1 = 0, s2 = 0, s3 = 0;
    for (int j = beg + lane; j < end; j += 32) {
        int s = g_src[j];
        float4 as4 = *(const float4*)(g_als + s * 4);
        float4 ex;
        ex.x = __expf(leaky(as4.x + ad.x) - m0);
        ex.y = __expf(leaky(as4.y + ad.y) - m1);
        ex.z = __expf(leaky(as4.z + ad.z) - m2);
        ex.w = __expf(leaky(as4.w + ad.w) - m3);
        *(float4*)(g_alpha + (long)j * 4) = ex;
        s0 += ex.x; s1 += ex.y; s2 += ex.z; s3 += ex.w;
    }
#pragma unroll
    for (int off = 16; off > 0; off >>= 1) {
        s0 += __shfl_xor_sync(0xffffffffu, s0, off);
        s1 += __shfl_xor_sync(0xffffffffu, s1, off);
        s2 += __shfl_xor_sync(0xffffffffu, s2, off);
        s3 += __shfl_xor_sync(0xffffffffu, s3, off);
    }
    float i0 = 1.0f / (s0 + 1e-16f), i1 = 1.0f / (s1 + 1e-16f);
    float i2 = 1.0f / (s2 + 1e-16f), i3 = 1.0f / (s3 + 1e-16f);
    for (int j = beg + lane; j < end; j += 32) {
        float4 ex = *(const float4*)(g_alpha + (long)j * 4);
        ex.x *= i0; ex.y *= i1; ex.z *= i2; ex.w *= i3;
        *(float4*)(g_alpha + (long)j * 4) = ex;
        int eid = g_eid[j];
        *(float4*)(alpha_out + (long)eid * 4) = ex;
    }
}

// ---------------- GAT aggregate (concat): block(256) per node ----------------
__global__ void k_agg_concat(const float* __restrict__ xw, const float* __restrict__ b,
                             float* __restrict__ out) {
    int n = blockIdx.x, t = threadIdx.x;
    int h = t >> 6;
    int beg = g_rowptr[n], end = g_rowptr[n + 1];
    float acc = 0.0f;
    for (int j = beg; j < end; j++) {
        int s = g_src[j];
        float a = g_alpha[(long)j * 4 + h];
        acc = fmaf(a, xw[(long)s * 256 + t], acc);
    }
    out[(long)n * 256 + t] = fmaxf(acc + b[t], 0.0f);
}

// ---------------- GAT aggregate (mean over heads): block(256) per node ----------------
template <bool RELU>
__global__ void k_agg_mean(const float* __restrict__ xw, const float* __restrict__ b,
                           float* __restrict__ out) {
    __shared__ float sm[256];
    int n = blockIdx.x, t = threadIdx.x;
    int h = t >> 6;
    int beg = g_rowptr[n], end = g_rowptr[n + 1];
    float acc = 0.0f;
    for (int j = beg; j < end; j++) {
        int s = g_src[j];
        float a = g_alpha[(long)j * 4 + h];
        acc = fmaf(a, xw[(long)s * 256 + t], acc);
    }
    sm[t] = acc;
    __syncthreads();
    if (t < 64) {
        float v = (sm[t] + sm[t + 64] + sm[t + 128] + sm[t + 192]) * 0.25f + b[t];
        if (RELU) v = fmaxf(v, 0.0f);
        out[(long)n * 64 + t] = v;
    }
}

// ---------------- host driver ----------------
extern "C" void kernel_launch(void* const* d_in, const int* in_sizes, int n_in,
                              void* d_out, int out_size) {
    const float* x        = (const float*)d_in[0];
    const int*   ei       = (const int*)d_in[1];
    const float* gcn_W    = (const float*)d_in[2];
    const float* gcn_b    = (const float*)d_in[3];
    const float* gat1_W   = (const float*)d_in[4];
    const float* gat1_as  = (const float*)d_in[5];
    const float* gat1_ad  = (const float*)d_in[6];
    const float* gat1_b   = (const float*)d_in[7];
    const float* gat2_W   = (const float*)d_in[8];
    const float* gat2_as  = (const float*)d_in[9];
    const float* gat2_ad  = (const float*)d_in[10];
    const float* gat2_b   = (const float*)d_in[11];
    const float* mean_W   = (const float*)d_in[12];
    const float* mean_as  = (const float*)d_in[13];
    const float* mean_ad  = (const float*)d_in[14];
    const float* mean_b   = (const float*)d_in[15];
    const float* std_W    = (const float*)d_in[16];
    const float* std_as   = (const float*)d_in[17];
    const float* std_ad   = (const float*)d_in[18];
    const float* std_b    = (const float*)d_in[19];

    float* out = (float*)d_out;
    float* o_zmean = out;                     // 20000*64
    float* o_zstd  = out + 1280000;           // 20000*64
    float* o_a1    = out + 2560000;           // 340000*4
    float* o_a2    = out + 3920000;
    float* o_am    = out + 5280000;
    float* o_as    = out + 6640000;

    // resolve device-symbol scratch addresses
    float *p_xw, *p_h0, *p_h1, *p_h2;
    cudaGetSymbolAddress((void**)&p_xw, g_xw);
    cudaGetSymbolAddress((void**)&p_h0, g_h0);
    cudaGetSymbolAddress((void**)&p_h1, g_h1);
    cudaGetSymbolAddress((void**)&p_h2, g_h2);

    const int EB = 256, EG = (NEP + EB - 1) / EB;

    // graph build (shared by all layers)
    k_zero_deg<<<80, 256>>>();
    k_hist<<<EG, EB>>>(ei);
    k_scan<<<1, 1024>>>();
    k_scatter<<<EG, EB>>>(ei);

    // Layer 0: GCN + relu
    launch_gemm(x, gcn_W, p_xw, NN, 128, 64);
    k_gcn_agg<<<NN, 64>>>(p_xw, gcn_b, p_h0);

    // Layer 1: GAT concat + relu
    launch_gemm(p_h0, gat1_W, p_xw, NN, 64, 256);
    k_coef<<<NN, 64>>>(p_xw, gat1_as, gat1_ad);
    k_softmax<<<NN / 4, 128>>>(o_a1);
    k_agg_concat<<<NN, 256>>>(p_xw, gat1_b, p_h1);

    // Layer 2: GAT mean + relu
    launch_gemm(p_h1, gat2_W, p_xw, NN, 256, 256);
    k_coef<<<NN, 64>>>(p_xw, gat2_as, gat2_ad);
    k_softmax<<<NN / 4, 128>>>(o_a2);
    k_agg_mean<true><<<NN, 256>>>(p_xw, gat2_b, p_h2);

    // Layer 3: mean head (no relu)
    launch_gemm(p_h2, mean_W, p_xw, NN, 64, 256);
    k_coef<<<NN, 64>>>(p_xw, mean_as, mean_ad);
    k_softmax<<<NN / 4, 128>>>(o_am);
    k_agg_mean<false><<<NN, 256>>>(p_xw, mean_b, o_zmean);

    // Layer 4: std head (no relu)
    launch_gemm(p_h2, std_W, p_xw, NN, 64, 256);
    k_coef<<<NN, 64>>>(p_xw, std_as, std_ad);
    k_softmax<<<NN / 4, 128>>>(o_as);
    k_agg_mean<false><<<NN, 256>>>(p_xw, std_b, o_zstd);
}

// round 3
// speedup vs baseline: 1.1816x; 1.1816x over previous
#include <cuda_runtime.h>
#include <math.h>

#define NN 20000
#define NE 320000
#define NEP 340000      // NE + NN self loops
#define NEG_SLOPE 0.2f

#define BM 128
#define BN 64
#define BK 16

// ---------------- scratch (static device globals; no runtime alloc) ----------------
__device__ int   g_deg[NN];
__device__ int   g_rowptr[NN + 1];
__device__ int   g_wptr[NN];
__device__ float g_dis[NN];
__device__ int   g_src[NEP];
__device__ int   g_eid[NEP];
__device__ float g_xw[NN * 512];        // widest GEMM output (fused heads)
__device__ float g_h0[NN * 64];
__device__ float g_h1[NN * 256];
__device__ float g_h2[NN * 64];
__device__ float g_als[NN * 8];
__device__ float g_ald[NN * 8];
__device__ float g_alpha[(long)NEP * 8];

// ---------------- graph build ----------------
__global__ void k_zero_deg() {
    for (int i = blockIdx.x * blockDim.x + threadIdx.x; i < NN; i += gridDim.x * blockDim.x)
        g_deg[i] = 0;
}

__global__ void k_hist(const int* __restrict__ ei) {
    for (int e = blockIdx.x * blockDim.x + threadIdx.x; e < NEP; e += gridDim.x * blockDim.x) {
        int d = (e < NE) ? ei[NE + e] : (e - NE);
        atomicAdd(&g_deg[d], 1);
    }
}

__global__ void k_scan() {
    __shared__ int tmp[1024];
    const int tid = threadIdx.x;
    const int CH = (NN + 1023) / 1024;
    const int base = tid * CH;
    int sum = 0;
    for (int i = 0; i < CH; i++) {
        int n = base + i;
        if (n < NN) sum += g_deg[n];
    }
    tmp[tid] = sum;
    __syncthreads();
    for (int off = 1; off < 1024; off <<= 1) {
        int v = (tid >= off) ? tmp[tid - off] : 0;
        __syncthreads();
        tmp[tid] += v;
        __syncthreads();
    }
    int run = tmp[tid] - sum;
    for (int i = 0; i < CH; i++) {
        int n = base + i;
        if (n < NN) {
            int c = g_deg[n];
            g_rowptr[n] = run;
            g_wptr[n]   = run;
            g_dis[n]    = (c > 0) ? rsqrtf((float)c) : 0.0f;
            run += c;
        }
    }
    if (tid == 1023) g_rowptr[NN] = run;
}

__global__ void k_scatter(const int* __restrict__ ei) {
    for (int e = blockIdx.x * blockDim.x + threadIdx.x; e < NEP; e += gridDim.x * blockDim.x) {
        int s, d;
        if (e < NE) { s = ei[e]; d = ei[NE + e]; }
        else        { s = e - NE; d = e - NE; }
        int pos = atomicAdd(&g_wptr[d], 1);
        g_src[pos] = s;
        g_eid[pos] = e;
    }
}

// ---------------- GEMM: C[M,N] = A[M,K] @ W[K,N], W split into two NW-wide halves ----------------
// 128x64 tile, 256 threads, 8x4 per thread, double-buffered smem, reg prefetch.
__global__ __launch_bounds__(256) void k_gemm(
    const float* __restrict__ A, const float* __restrict__ W0,
    const float* __restrict__ W1, int NW,
    float* __restrict__ C, int M, int K, int N)
{
    __shared__ float As[2][BK][BM];   // 16 KB
    __shared__ float Ws[2][BK][BN];   //  8 KB
    const int tid  = threadIdx.x;
    const int row0 = blockIdx.x * BM;
    const int col0 = blockIdx.y * BN;
    const int tx = tid & 15, ty = tid >> 4;

    const int a_row = tid >> 1;
    const int a_cb  = (tid & 1) * 8;
    const int w_r   = tid >> 4;
    const int w_c   = (tid & 15) * 4;
    const int a_gr  = row0 + a_row;
    const bool a_ok = (a_gr < M);
    const float* a_ptr = A + (long)a_gr * K + a_cb;
    const int wcol = col0 + w_c;
    const float* w_ptr = (wcol < NW) ? (W0 + wcol) : (W1 + wcol - NW);

    float acc[8][4];
#pragma unroll
    for (int i = 0; i < 8; i++)
#pragma unroll
        for (int j = 0; j < 4; j++) acc[i][j] = 0.0f;

    // prologue: load k0 = 0 into buffer 0
    {
        float4 pa0 = make_float4(0,0,0,0), pa1 = make_float4(0,0,0,0);
        if (a_ok) {
            pa0 = *(const float4*)(a_ptr);
            pa1 = *(const float4*)(a_ptr + 4);
        }
        float4 pw = *(const float4*)(w_ptr + (long)w_r * NW);
        As[0][a_cb+0][a_row]=pa0.x; As[0][a_cb+1][a_row]=pa0.y;
        As[0][a_cb+2][a_row]=pa0.z; As[0][a_cb+3][a_row]=pa0.w;
        As[0][a_cb+4][a_row]=pa1.x; As[0][a_cb+5][a_row]=pa1.y;
        As[0][a_cb+6][a_row]=pa1.z; As[0][a_cb+7][a_row]=pa1.w;
        *(float4*)&Ws[0][w_r][w_c] = pw;
    }
    __syncthreads();

    int buf = 0;
    for (int k0 = 0; k0 < K; k0 += BK) {
        const bool pre = (k0 + BK < K);
        float4 pa0 = make_float4(0,0,0,0), pa1 = make_float4(0,0,0,0), pw = make_float4(0,0,0,0);
        if (pre) {
            if (a_ok) {
                pa0 = *(const float4*)(a_ptr + k0 + BK);
                pa1 = *(const float4*)(a_ptr + k0 + BK + 4);
            }
            pw = *(const float4*)(w_ptr + (long)(k0 + BK + w_r) * NW);
        }
#pragma unroll
        for (int k = 0; k < BK; k++) {
            float4 a0 = *(const float4*)&As[buf][k][ty * 8];
            float4 a1 = *(const float4*)&As[buf][k][ty * 8 + 4];
            float4 b  = *(const float4*)&Ws[buf][k][tx * 4];
            float av[8] = {a0.x,a0.y,a0.z,a0.w,a1.x,a1.y,a1.z,a1.w};
            float bv[4] = {b.x,b.y,b.z,b.w};
#pragma unroll
            for (int i = 0; i < 8; i++)
#pragma unroll
                for (int j = 0; j < 4; j++)
                    acc[i][j] = fmaf(av[i], bv[j], acc[i][j]);
        }
        if (pre) {
            int nb = buf ^ 1;
            As[nb][a_cb+0][a_row]=pa0.x; As[nb][a_cb+1][a_row]=pa0.y;
            As[nb][a_cb+2][a_row]=pa0.z; As[nb][a_cb+3][a_row]=pa0.w;
            As[nb][a_cb+4][a_row]=pa1.x; As[nb][a_cb+5][a_row]=pa1.y;
            As[nb][a_cb+6][a_row]=pa1.z; As[nb][a_cb+7][a_row]=pa1.w;
            *(float4*)&Ws[nb][w_r][w_c] = pw;
        }
        __syncthreads();
        buf ^= 1;
    }

#pragma unroll
    for (int i = 0; i < 8; i++) {
        int gr = row0 + ty * 8 + i;
        if (gr < M) {
            float4 v = make_float4(acc[i][0], acc[i][1], acc[i][2], acc[i][3]);
            *(float4*)&C[(long)gr * N + col0 + tx * 4] = v;
        }
    }
}

static inline void launch_gemm(const float* A, const float* W0, const float* W1, int NW,
                               float* C, int M, int K, int N) {
    dim3 grid((M + BM - 1) / BM, N / BN);
    k_gemm<<<grid, 256>>>(A, W0, W1, NW, C, M, K, N);
}

// ---------------- GCN aggregate: block(64) per node ----------------
__global__ void k_gcn_agg(const float* __restrict__ xw, const float* __restrict__ b,
                          float* __restrict__ out) {
    int n = blockIdx.x, t = threadIdx.x;
    int beg = g_rowptr[n], end = g_rowptr[n + 1];
    float dn = g_dis[n];
    float acc = 0.0f;
    for (int j = beg; j < end; j++) {
        int s = g_src[j];
        acc = fmaf(dn * g_dis[s], xw[s * 64 + t], acc);
    }
    out[n * 64 + t] = fmaxf(acc + b[t], 0.0f);
}

// ---------------- attention coefficients ----------------
// 4-head layer (xw 256-wide): 4 nodes per 256-thread block
__global__ void k_coef4(const float* __restrict__ xw, const float* __restrict__ asrc,
                        const float* __restrict__ adst) {
    int t = threadIdx.x;
    int n = blockIdx.x * 4 + (t >> 6);
    int u = t & 63;
    int h = u >> 4, q = u & 15;
    const float4 v  = *(const float4*)(xw + (long)n * 256 + h * 64 + q * 4);
    const float4 ws = *(const float4*)(asrc + h * 64 + q * 4);
    const float4 wd = *(const float4*)(adst + h * 64 + q * 4);
    float ps = v.x * ws.x + v.y * ws.y + v.z * ws.z + v.w * ws.w;
    float pd = v.x * wd.x + v.y * wd.y + v.z * wd.z + v.w * wd.w;
#pragma unroll
    for (int off = 8; off > 0; off >>= 1) {
        ps += __shfl_down_sync(0xffffffffu, ps, off, 16);
        pd += __shfl_down_sync(0xffffffffu, pd, off, 16);
    }
    if (q == 0) {
        g_als[n * 4 + h] = ps;
        g_ald[n * 4 + h] = pd;
    }
}

// 8-head fused (xw 512-wide, heads 0-3 mean, 4-7 std): 2 nodes per 256-thread block
__global__ void k_coef8(const float* __restrict__ xw,
                        const float* __restrict__ as_m, const float* __restrict__ ad_m,
                        const float* __restrict__ as_s, const float* __restrict__ ad_s) {
    int t = threadIdx.x;
    int n = blockIdx.x * 2 + (t >> 7);
    int u = t & 127;
    int h = u >> 4, q = u & 15;
    const float* aws = (h < 4) ? (as_m + h * 64) : (as_s + (h - 4) * 64);
    const float* awd = (h < 4) ? (ad_m + h * 64) : (ad_s + (h - 4) * 64);
    const float4 v  = *(const float4*)(xw + (long)n * 512 + h * 64 + q * 4);
    const float4 ws = *(const float4*)(aws + q * 4);
    const float4 wd = *(const float4*)(awd + q * 4);
    float ps = v.x * ws.x + v.y * ws.y + v.z * ws.z + v.w * ws.w;
    float pd = v.x * wd.x + v.y * wd.y + v.z * wd.z + v.w * wd.w;
#pragma unroll
    for (int off = 8; off > 0; off >>= 1) {
        ps += __shfl_down_sync(0xffffffffu, ps, off, 16);
        pd += __shfl_down_sync(0xffffffffu, pd, off, 16);
    }
    if (q == 0) {
        g_als[n * 8 + h] = ps;
        g_ald[n * 8 + h] = pd;
    }
}

__device__ __forceinline__ float leaky(float x) { return x > 0.0f ? x : NEG_SLOPE * x; }

// ---------------- segment softmax: 1 warp per node, H heads ----------------
template <int H>
__global__ void k_softmax(float* __restrict__ out0, float* __restrict__ out1) {
    int warp = threadIdx.x >> 5, lane = threadIdx.x & 31;
    int n = blockIdx.x * 4 + warp;
    if (n >= NN) return;
    int beg = g_rowptr[n], end = g_rowptr[n + 1];
    float ad[H];
#pragma unroll
    for (int h = 0; h < H; h++) ad[h] = g_ald[n * H + h];

    float m[H];
#pragma unroll
    for (int h = 0; h < H; h++) m[h] = -1e30f;
    for (int j = beg + lane; j < end; j += 32) {
        int s = g_src[j];
#pragma unroll
        for (int h = 0; h < H; h++)
            m[h] = fmaxf(m[h], leaky(g_als[s * H + h] + ad[h]));
    }
#pragma unroll
    for (int h = 0; h < H; h++)
#pragma unroll
        for (int off = 16; off > 0; off >>= 1)
            m[h] = fmaxf(m[h], __shfl_xor_sync(0xffffffffu, m[h], off));

    float sum[H];
#pragma unroll
    for (int h = 0; h < H; h++) sum[h] = 0.0f;
    for (int j = beg + lane; j < end; j += 32) {
        int s = g_src[j];
        float ex[H];
#pragma unroll
        for (int h = 0; h < H; h++) {
            ex[h] = __expf(leaky(g_als[s * H + h] + ad[h]) - m[h]);
            sum[h] += ex[h];
        }
#pragma unroll
        for (int v = 0; v < H / 4; v++)
            *(float4*)&g_alpha[(long)j * H + v * 4] =
                make_float4(ex[v*4], ex[v*4+1], ex[v*4+2], ex[v*4+3]);
    }
#pragma unroll
    for (int h = 0; h < H; h++)
#pragma unroll
        for (int off = 16; off > 0; off >>= 1)
            sum[h] += __shfl_xor_sync(0xffffffffu, sum[h], off);

    float inv[H];
#pragma unroll
    for (int h = 0; h < H; h++) inv[h] = 1.0f / (sum[h] + 1e-16f);

    for (int j = beg + lane; j < end; j += 32) {
        float ex[H];
#pragma unroll
        for (int v = 0; v < H / 4; v++) {
            float4 e4 = *(const float4*)&g_alpha[(long)j * H + v * 4];
            ex[v*4] = e4.x; ex[v*4+1] = e4.y; ex[v*4+2] = e4.z; ex[v*4+3] = e4.w;
        }
#pragma unroll
        for (int h = 0; h < H; h++) ex[h] *= inv[h];
#pragma unroll
        for (int v = 0; v < H / 4; v++)
            *(float4*)&g_alpha[(long)j * H + v * 4] =
                make_float4(ex[v*4], ex[v*4+1], ex[v*4+2], ex[v*4+3]);
        int eid = g_eid[j];
        *(float4*)&out0[(long)eid * 4] = make_float4(ex[0], ex[1], ex[2], ex[3]);
        if (H == 8)
            *(float4*)&out1[(long)eid * 4] = make_float4(ex[4], ex[5], ex[6], ex[7]);
    }
}

// ---------------- GAT aggregate (concat): block(256) per node ----------------
__global__ void k_agg_concat(const float* __restrict__ xw, const float* __restrict__ b,
                             float* __restrict__ out) {
    int n = blockIdx.x, t = threadIdx.x;
    int h = t >> 6;
    int beg = g_rowptr[n], end = g_rowptr[n + 1];
    float acc = 0.0f;
    for (int j = beg; j < end; j++) {
        int s = g_src[j];
        float a = g_alpha[(long)j * 4 + h];
        acc = fmaf(a, xw[(long)s * 256 + t], acc);
    }
    out[(long)n * 256 + t] = fmaxf(acc + b[t], 0.0f);
}

// ---------------- GAT aggregate (mean over 4 heads): block(256) per node ----------------
__global__ void k_agg_mean(const float* __restrict__ xw, const float* __restrict__ b,
                           float* __restrict__ out) {
    __shared__ float sm[256];
    int n = blockIdx.x, t = threadIdx.x;
    int h = t >> 6;
    int beg = g_rowptr[n], end = g_rowptr[n + 1];
    float acc = 0.0f;
    for (int j = beg; j < end; j++) {
        int s = g_src[j];
        float a = g_alpha[(long)j * 4 + h];
        acc = fmaf(a, xw[(long)s * 256 + t], acc);
    }
    sm[t] = acc;
    __syncthreads();
    if (t < 64) {
        float v = (sm[t] + sm[t + 64] + sm[t + 128] + sm[t + 192]) * 0.25f + b[t];
        out[(long)n * 64 + t] = fmaxf(v, 0.0f);
    }
}

// ---------------- fused dual-head aggregate (8 heads, 512-wide xw): block(512) ----------------
__global__ void k_agg_dual(const float* __restrict__ xw,
                           const float* __restrict__ b_m, const float* __restrict__ b_s,
                           float* __restrict__ out_m, float* __restrict__ out_s) {
    __shared__ float sm[512];
    int n = blockIdx.x, t = threadIdx.x;
    int h = t >> 6;
    int beg = g_rowptr[n], end = g_rowptr[n + 1];
    float acc = 0.0f;
    for (int j = beg; j < end; j++) {
        int s = g_src[j];
        float a = g_alpha[(long)j * 8 + h];
        acc = fmaf(a, xw[(long)s * 512 + t], acc);
    }
    sm[t] = acc;
    __syncthreads();
    if (t < 64) {
        float vm = (sm[t] + sm[t + 64] + sm[t + 128] + sm[t + 192]) * 0.25f + b_m[t];
        out_m[(long)n * 64 + t] = vm;
    } else if (t < 128) {
        int u = t - 64;
        float vs = (sm[256 + u] + sm[320 + u] + sm[384 + u] + sm[448 + u]) * 0.25f + b_s[u];
        out_s[(long)n * 64 + u] = vs;
    }
}

// ---------------- host driver ----------------
extern "C" void kernel_launch(void* const* d_in, const int* in_sizes, int n_in,
                              void* d_out, int out_size) {
    const float* x        = (const float*)d_in[0];
    const int*   ei       = (const int*)d_in[1];
    const float* gcn_W    = (const float*)d_in[2];
    const float* gcn_b    = (const float*)d_in[3];
    const float* gat1_W   = (const float*)d_in[4];
    const float* gat1_as  = (const float*)d_in[5];
    const float* gat1_ad  = (const float*)d_in[6];
    const float* gat1_b   = (const float*)d_in[7];
    const float* gat2_W   = (const float*)d_in[8];
    const float* gat2_as  = (const float*)d_in[9];
    const float* gat2_ad  = (const float*)d_in[10];
    const float* gat2_b   = (const float*)d_in[11];
    const float* mean_W   = (const float*)d_in[12];
    const float* mean_as  = (const float*)d_in[13];
    const float* mean_ad  = (const float*)d_in[14];
    const float* mean_b   = (const float*)d_in[15];
    const float* std_W    = (const float*)d_in[16];
    const float* std_as   = (const float*)d_in[17];
    const float* std_ad   = (const float*)d_in[18];
    const float* std_b    = (const float*)d_in[19];

    float* out = (float*)d_out;
    float* o_zmean = out;
    float* o_zstd  = out + 1280000;
    float* o_a1    = out + 2560000;
    float* o_a2    = out + 3920000;
    float* o_am    = out + 5280000;
    float* o_as    = out + 6640000;

    float *p_xw, *p_h0, *p_h1, *p_h2;
    cudaGetSymbolAddress((void**)&p_xw, g_xw);
    cudaGetSymbolAddress((void**)&p_h0, g_h0);
    cudaGetSymbolAddress((void**)&p_h1, g_h1);
    cudaGetSymbolAddress((void**)&p_h2, g_h2);

    const int EB = 256, EG = (NEP + EB - 1) / EB;

    // graph build
    k_zero_deg<<<80, 256>>>();
    k_hist<<<EG, EB>>>(ei);
    k_scan<<<1, 1024>>>();
    k_scatter<<<EG, EB>>>(ei);

    // Layer 0: GCN + relu
    launch_gemm(x, gcn_W, gcn_W, 64, p_xw, NN, 128, 64);
    k_gcn_agg<<<NN, 64>>>(p_xw, gcn_b, p_h0);

    // Layer 1: GAT concat + relu
    launch_gemm(p_h0, gat1_W, gat1_W, 256, p_xw, NN, 64, 256);
    k_coef4<<<NN / 4, 256>>>(p_xw, gat1_as, gat1_ad);
    k_softmax<4><<<NN / 4, 128>>>(o_a1, nullptr);
    k_agg_concat<<<NN, 256>>>(p_xw, gat1_b, p_h1);

    // Layer 2: GAT mean + relu
    launch_gemm(p_h1, gat2_W, gat2_W, 256, p_xw, NN, 256, 256);
    k_coef4<<<NN / 4, 256>>>(p_xw, gat2_as, gat2_ad);
    k_softmax<4><<<NN / 4, 128>>>(o_a2, nullptr);
    k_agg_mean<<<NN, 256>>>(p_xw, gat2_b, p_h2);

    // Layers 3+4 fused: mean & std heads
    launch_gemm(p_h2, mean_W, std_W, 256, p_xw, NN, 64, 512);
    k_coef8<<<NN / 2, 256>>>(p_xw, mean_as, mean_ad, std_as, std_ad);
    k_softmax<8><<<NN / 4, 128>>>(o_am, o_as);
    k_agg_dual<<<NN, 512>>>(p_xw, mean_b, std_b, o_zmean, o_zstd);
}